// round 3
// baseline (speedup 1.0000x reference)
#include <cuda_runtime.h>
#include <cuda_bf16.h>

// Problem constants
#define BB 32
#define NN 1024
#define FF 128
#define DD 128
#define DK 0.08838834764831843f  // 128^{-0.5}

#define NBLK 128   // 4 chunk-blocks per batch, 256 rows each
#define NTHR 256

// Scratch
__device__ float g_spart[BB * 4 * FF];
__device__ float g_agg[BB * NN];
__device__ float g_w[BB * NN];
__device__ float g_wsum[BB];
__device__ unsigned g_bar;   // monotonic ticket counter (replay-safe)

// ---------------------------------------------------------------------------
// Software grid barrier: monotonic ticket, generation derived from ticket.
// All NBLK blocks must be co-resident (NBLK=128 <= 148 SMs, tiny smem/regs).
// ---------------------------------------------------------------------------
__device__ __forceinline__ void grid_barrier() {
    __threadfence();           // release all prior writes (+ L1 invalidate)
    __syncthreads();
    if (threadIdx.x == 0) {
        unsigned ticket = atomicAdd(&g_bar, 1u);
        unsigned target = (ticket / NBLK + 1u) * NBLK;
        unsigned cur;
        do {
            asm volatile("ld.global.acquire.gpu.u32 %0, [%1];"
                         : "=r"(cur) : "l"(&g_bar));
        } while (cur < target);
    }
    __syncthreads();
    __threadfence();           // acquire side: fresh view for all threads
}

__global__ __launch_bounds__(NTHR) void k_fused(const float* __restrict__ aq,
                                                const float* __restrict__ mask,
                                                const float* __restrict__ Wq,
                                                const float* __restrict__ bq,
                                                const float* __restrict__ Wk,
                                                const float* __restrict__ bk,
                                                const float* __restrict__ Wv,
                                                const float* __restrict__ bv,
                                                float* __restrict__ out_attn,
                                                float* __restrict__ out_ctx) {
    int blk = blockIdx.x;
    int b   = blk >> 2;        // batch
    int ch  = blk & 3;         // 256-row chunk
    int tid = threadIdx.x;
    int lane = tid & 31;
    int warp = tid >> 5;       // 0..7

    __shared__ float4 sh4[8][32];    // 4 KB reduce scratch
    __shared__ float  s_sh[FF];
    __shared__ float  ksum_sh[DD];
    __shared__ float  wvec_sh[FF];
    __shared__ float  t_sh[FF];
    __shared__ float  red[8];
    __shared__ float  bc[2];         // [0]=cbias or max, [1]=sum

    const float4* aq4 = reinterpret_cast<const float4*>(aq);

    // ---- P0: zero out_ctx (poisoned by harness) ----
    if (ch == 0 && tid < DD) out_ctx[b * DD + tid] = 0.f;

    // ---- P1: row-sum own 256 rows -> g_spart[b][ch] ----
    {
        int row0 = ch * 256 + warp * 32;
        const float4* base = aq4 + ((size_t)b * NN + row0) * (FF / 4);
        float4 acc = make_float4(0.f, 0.f, 0.f, 0.f);
        for (int j0 = 0; j0 < 32; j0 += 8) {
            float4 v[8];
#pragma unroll
            for (int jj = 0; jj < 8; jj++)
                v[jj] = base[(j0 + jj) * (FF / 4) + lane];
#pragma unroll
            for (int jj = 0; jj < 8; jj++) {
                acc.x += v[jj].x; acc.y += v[jj].y;
                acc.z += v[jj].z; acc.w += v[jj].w;
            }
        }
        sh4[warp][lane] = acc;
        __syncthreads();
        if (warp == 0) {
            float4 r = sh4[0][lane];
#pragma unroll
            for (int w = 1; w < 8; w++) {
                float4 x = sh4[w][lane];
                r.x += x.x; r.y += x.y; r.z += x.z; r.w += x.w;
            }
            reinterpret_cast<float4*>(&g_spart[(b * 4 + ch) * FF])[lane] = r;
        }
    }

    grid_barrier();   // ---- all g_spart ready ----

    // ---- P2: (redundant per block) s, ksum, wvec, cbias for batch b ----
    if (tid < FF) {
        float s = 0.f;
#pragma unroll
        for (int c2 = 0; c2 < 4; c2++)
            s += g_spart[(b * 4 + c2) * FF + tid];
        s_sh[tid] = s;
    }
    __syncthreads();
    if (tid < DD) {
        float acc = 0.f;
#pragma unroll 8
        for (int f = 0; f < FF; f++)
            acc += s_sh[f] * Wk[(size_t)f * DD + tid];
        ksum_sh[tid] = acc + (float)NN * bk[tid];
    }
    __syncthreads();
    // wvec: 8 warps x 16 rows, warp-dot
    for (int j = 0; j < 16; j++) {
        int f = warp * 16 + j;
        float p = 0.f;
#pragma unroll
        for (int dd = lane; dd < DD; dd += 32)
            p += Wq[(size_t)f * DD + dd] * ksum_sh[dd];
        for (int off = 16; off; off >>= 1)
            p += __shfl_xor_sync(0xffffffffu, p, off);
        if (lane == 0) wvec_sh[f] = p;
    }
    if (warp == 0) {  // cbias
        float p = 0.f;
#pragma unroll
        for (int dd = lane; dd < DD; dd += 32)
            p += bq[dd] * ksum_sh[dd];
        for (int off = 16; off; off >>= 1)
            p += __shfl_xor_sync(0xffffffffu, p, off);
        if (lane == 0) bc[0] = p;
    }
    __syncthreads();

    // ---- P3: agg logits for own 256 rows (aq from L2/L1) ----
    {
        float4 wv4 = reinterpret_cast<const float4*>(wvec_sh)[lane];
        float cb = bc[0];
        int row0 = ch * 256 + warp * 32;
        const float4* base = aq4 + ((size_t)b * NN + row0) * (FF / 4);
        for (int j0 = 0; j0 < 32; j0 += 8) {
            float4 v[8];
#pragma unroll
            for (int jj = 0; jj < 8; jj++)
                v[jj] = base[(j0 + jj) * (FF / 4) + lane];
#pragma unroll
            for (int jj = 0; jj < 8; jj++) {
                float d = v[jj].x * wv4.x + v[jj].y * wv4.y
                        + v[jj].z * wv4.z + v[jj].w * wv4.w;
                for (int off = 16; off; off >>= 1)
                    d += __shfl_xor_sync(0xffffffffu, d, off);
                if (lane == 0) {
                    int n = row0 + j0 + jj;
                    float m = mask[(size_t)b * NN + n];
                    g_agg[(size_t)b * NN + n] =
                        (m != 0.f) ? (DK * (d + cb)) : -1e9f;
                }
            }
        }
    }

    grid_barrier();   // ---- all agg ready ----

    // ---- P4: softmax per batch (ch==0 blocks only) ----
    if (ch == 0) {
        float4 a4 = reinterpret_cast<const float4*>(&g_agg[(size_t)b * NN])[tid];
        float mx = fmaxf(fmaxf(a4.x, a4.y), fmaxf(a4.z, a4.w));
        for (int off = 16; off; off >>= 1)
            mx = fmaxf(mx, __shfl_xor_sync(0xffffffffu, mx, off));
        if (lane == 0) red[warp] = mx;
        __syncthreads();
        float m2 = red[lane & 7];
        for (int off = 4; off; off >>= 1)
            m2 = fmaxf(m2, __shfl_xor_sync(0xffffffffu, m2, off));
        mx = __shfl_sync(0xffffffffu, m2, 0);

        float4 e4;
        e4.x = expf(a4.x - mx); e4.y = expf(a4.y - mx);
        e4.z = expf(a4.z - mx); e4.w = expf(a4.w - mx);
        float ssum = e4.x + e4.y + e4.z + e4.w;
        for (int off = 16; off; off >>= 1)
            ssum += __shfl_xor_sync(0xffffffffu, ssum, off);
        __syncthreads();
        if (lane == 0) red[warp] = ssum;
        __syncthreads();
        float s2 = red[lane & 7];
        for (int off = 4; off; off >>= 1)
            s2 += __shfl_xor_sync(0xffffffffu, s2, off);
        float inv = 1.0f / __shfl_sync(0xffffffffu, s2, 0);

        float4 at4;
        at4.x = e4.x * inv; at4.y = e4.y * inv;
        at4.z = e4.z * inv; at4.w = e4.w * inv;
        reinterpret_cast<float4*>(&out_attn[(size_t)b * NN])[tid] = at4;

        float4 m4 = reinterpret_cast<const float4*>(&mask[(size_t)b * NN])[tid];
        float4 w4;
        w4.x = m4.x * at4.x; w4.y = m4.y * at4.y;
        w4.z = m4.z * at4.z; w4.w = m4.w * at4.w;
        reinterpret_cast<float4*>(&g_w[(size_t)b * NN])[tid] = w4;

        float ws = w4.x + w4.y + w4.z + w4.w;
        for (int off = 16; off; off >>= 1)
            ws += __shfl_xor_sync(0xffffffffu, ws, off);
        __syncthreads();
        if (lane == 0) red[warp] = ws;
        __syncthreads();
        if (tid == 0) {
            float t = 0.f;
#pragma unroll
            for (int w = 0; w < 8; w++) t += red[w];
            g_wsum[b] = t;
        }
    }

    grid_barrier();   // ---- w, wsum ready ----

    // ---- P5: weighted row-sum (own 256 rows) + partial ctx matvec ----
    {
        int row0 = ch * 256 + warp * 32;
        const float4* base = aq4 + ((size_t)b * NN + row0) * (FF / 4);
        const float* wp = &g_w[(size_t)b * NN + row0];
        float4 acc = make_float4(0.f, 0.f, 0.f, 0.f);
        for (int j0 = 0; j0 < 32; j0 += 8) {
            float4 v[8];
            float wb[8];
#pragma unroll
            for (int jj = 0; jj < 8; jj++) {
                v[jj] = base[(j0 + jj) * (FF / 4) + lane];
                wb[jj] = wp[j0 + jj];
            }
#pragma unroll
            for (int jj = 0; jj < 8; jj++) {
                acc.x += wb[jj] * v[jj].x;
                acc.y += wb[jj] * v[jj].y;
                acc.z += wb[jj] * v[jj].z;
                acc.w += wb[jj] * v[jj].w;
            }
        }
        sh4[warp][lane] = acc;
        __syncthreads();
        if (warp == 0) {
            float4 r = sh4[0][lane];
#pragma unroll
            for (int w = 1; w < 8; w++) {
                float4 x = sh4[w][lane];
                r.x += x.x; r.y += x.y; r.z += x.z; r.w += x.w;
            }
            reinterpret_cast<float4*>(t_sh)[lane] = r;
        }
        __syncthreads();

        if (tid < DD) {
            float accd = 0.f;
#pragma unroll 8
            for (int f = 0; f < FF; f++)
                accd += t_sh[f] * Wv[(size_t)f * DD + tid];
            if (ch == 0) accd += g_wsum[b] * bv[tid];
            atomicAdd(&out_ctx[(size_t)b * DD + tid], accd);
        }
    }
}

// ---------------------------------------------------------------------------
// Inputs: atom_query, mask, Wq, bq, Wk, bk, Wv, bv
// Output: attn [B*N] then context [B*D], float32.
// ---------------------------------------------------------------------------
extern "C" void kernel_launch(void* const* d_in, const int* in_sizes, int n_in,
                              void* d_out, int out_size) {
    const float* aq   = (const float*)d_in[0];
    const float* mask = (const float*)d_in[1];
    const float* Wq   = (const float*)d_in[2];
    const float* bq   = (const float*)d_in[3];
    const float* Wk   = (const float*)d_in[4];
    const float* bk   = (const float*)d_in[5];
    const float* Wv   = (const float*)d_in[6];
    const float* bv   = (const float*)d_in[7];

    float* out_attn = (float*)d_out;
    float* out_ctx  = out_attn + (size_t)BB * NN;

    k_fused<<<NBLK, NTHR>>>(aq, mask, Wq, bq, Wk, bk, Wv, bv,
                            out_attn, out_ctx);
}

// round 5
// speedup vs baseline: 1.3407x; 1.3407x over previous
#include <cuda_runtime.h>
#include <cuda_bf16.h>

// Problem constants
#define BB 32
#define NN 1024
#define FF 128
#define DD 128
#define DK 0.08838834764831843f  // 128^{-0.5}

#define NBLK 128   // 4 chunk-blocks per batch, 256 rows each
#define NTHR 1024  // 32 warps per block -> 50% occupancy, 1 CTA/SM

// Scratch
__device__ float g_spart[BB * 4 * FF];
__device__ float g_agg[BB * NN];
__device__ float g_w[BB * NN];
__device__ float g_wsum[BB];
__device__ unsigned g_bar;   // monotonic ticket counter (replay-safe)

// ---------------------------------------------------------------------------
// Software grid barrier: monotonic ticket, generation derived from ticket.
// All NBLK=128 blocks co-resident (1 CTA/SM on 148 SMs).
// ---------------------------------------------------------------------------
__device__ __forceinline__ void grid_barrier() {
    __threadfence();
    __syncthreads();
    if (threadIdx.x == 0) {
        unsigned ticket = atomicAdd(&g_bar, 1u);
        unsigned target = (ticket / NBLK + 1u) * NBLK;
        unsigned cur;
        do {
            asm volatile("ld.global.acquire.gpu.u32 %0, [%1];"
                         : "=r"(cur) : "l"(&g_bar));
        } while (cur < target);
    }
    __syncthreads();
    __threadfence();
}

__global__ __launch_bounds__(NTHR, 1) void k_fused(
        const float* __restrict__ aq,
        const float* __restrict__ mask,
        const float* __restrict__ Wq,
        const float* __restrict__ bq,
        const float* __restrict__ Wk,
        const float* __restrict__ bk,
        const float* __restrict__ Wv,
        const float* __restrict__ bv,
        float* __restrict__ out_attn,
        float* __restrict__ out_ctx) {
    int blk = blockIdx.x;
    int b   = blk >> 2;        // batch
    int ch  = blk & 3;         // 256-row chunk
    int tid = threadIdx.x;
    int lane = tid & 31;
    int warp = tid >> 5;       // 0..31, owns 8 rows

    __shared__ float4 sh4[32][32];   // 16 KB reduce scratch
    __shared__ float  s_sh[FF];
    __shared__ float  ksum_sh[DD];
    __shared__ float  wvec_sh[FF];
    __shared__ float  t_sh[FF];
    __shared__ float  red[32];
    __shared__ float  bc[2];

    const float4* aq4 = reinterpret_cast<const float4*>(aq);
    int row0 = ch * 256 + warp * 8;
    const float4* base = aq4 + ((size_t)b * NN + row0) * (FF / 4);

    // ---- P0: zero out_ctx (poisoned by harness) ----
    if (ch == 0 && tid < DD) out_ctx[b * DD + tid] = 0.f;

    // ---- P1: row-sum own 8 rows/warp -> g_spart[b][ch] ----
    {
        float4 v[8];
#pragma unroll
        for (int jj = 0; jj < 8; jj++)
            v[jj] = base[jj * (FF / 4) + lane];
        float4 acc = v[0];
#pragma unroll
        for (int jj = 1; jj < 8; jj++) {
            acc.x += v[jj].x; acc.y += v[jj].y;
            acc.z += v[jj].z; acc.w += v[jj].w;
        }
        sh4[warp][lane] = acc;
        __syncthreads();
        if (warp < 4) {     // 4 warps each reduce 8 partials
            float4 r = sh4[warp * 8][lane];
#pragma unroll
            for (int w = 1; w < 8; w++) {
                float4 x = sh4[warp * 8 + w][lane];
                r.x += x.x; r.y += x.y; r.z += x.z; r.w += x.w;
            }
            sh4[warp][lane] = r;   // safe: writing rows 0..3, read rows >= warp*8
        }
        __syncthreads();
        if (warp == 0) {
            float4 r = sh4[0][lane];
#pragma unroll
            for (int w = 1; w < 4; w++) {
                float4 x = sh4[w][lane];
                r.x += x.x; r.y += x.y; r.z += x.z; r.w += x.w;
            }
            reinterpret_cast<float4*>(&g_spart[(b * 4 + ch) * FF])[lane] = r;
        }
    }

    grid_barrier();   // ---- all g_spart ready ----

    // ---- P2: (redundant per block) s, ksum, wvec, cbias for batch b ----
    if (tid < FF) {
        float s = 0.f;
#pragma unroll
        for (int c2 = 0; c2 < 4; c2++)
            s += g_spart[(b * 4 + c2) * FF + tid];
        s_sh[tid] = s;
    }
    __syncthreads();
    if (tid < DD) {
        float acc = 0.f;
#pragma unroll 8
        for (int f = 0; f < FF; f++)
            acc += s_sh[f] * Wk[(size_t)f * DD + tid];
        ksum_sh[tid] = acc + (float)NN * bk[tid];
    }
    __syncthreads();
    // wvec: 32 warps x 4 rows, warp-dot
    {
#pragma unroll
        for (int j = 0; j < 4; j++) {
            int f = warp * 4 + j;
            float p = 0.f;
#pragma unroll
            for (int dd = lane; dd < DD; dd += 32)
                p += Wq[(size_t)f * DD + dd] * ksum_sh[dd];
            for (int off = 16; off; off >>= 1)
                p += __shfl_xor_sync(0xffffffffu, p, off);
            if (lane == 0) wvec_sh[f] = p;
        }
    }
    if (warp == 0) {  // cbias
        float p = 0.f;
#pragma unroll
        for (int dd = lane; dd < DD; dd += 32)
            p += bq[dd] * ksum_sh[dd];
        for (int off = 16; off; off >>= 1)
            p += __shfl_xor_sync(0xffffffffu, p, off);
        if (lane == 0) bc[0] = p;
    }
    __syncthreads();

    // ---- P3: agg logits for own 8 rows/warp (aq L2-resident) ----
    {
        float4 wv4 = reinterpret_cast<const float4*>(wvec_sh)[lane];
        float cb = bc[0];
        float4 v[8];
#pragma unroll
        for (int jj = 0; jj < 8; jj++)
            v[jj] = base[jj * (FF / 4) + lane];
#pragma unroll
        for (int jj = 0; jj < 8; jj++) {
            float d = v[jj].x * wv4.x + v[jj].y * wv4.y
                    + v[jj].z * wv4.z + v[jj].w * wv4.w;
            for (int off = 16; off; off >>= 1)
                d += __shfl_xor_sync(0xffffffffu, d, off);
            if (lane == 0) {
                int n = row0 + jj;
                float m = mask[(size_t)b * NN + n];
                g_agg[(size_t)b * NN + n] =
                    (m != 0.f) ? (DK * (d + cb)) : -1e9f;
            }
        }
    }

    grid_barrier();   // ---- all agg ready ----

    // ---- P4: softmax per batch (ch==0 blocks, 1 element/thread) ----
    if (ch == 0) {
        float a = g_agg[(size_t)b * NN + tid];
        float mx = a;
        for (int off = 16; off; off >>= 1)
            mx = fmaxf(mx, __shfl_xor_sync(0xffffffffu, mx, off));
        if (lane == 0) red[warp] = mx;
        __syncthreads();
        if (warp == 0) {
            float m2 = red[lane];
            for (int off = 16; off; off >>= 1)
                m2 = fmaxf(m2, __shfl_xor_sync(0xffffffffu, m2, off));
            if (lane == 0) bc[1] = m2;
        }
        __syncthreads();
        mx = bc[1];

        float e = expf(a - mx);
        float ssum = e;
        for (int off = 16; off; off >>= 1)
            ssum += __shfl_xor_sync(0xffffffffu, ssum, off);
        __syncthreads();
        if (lane == 0) red[warp] = ssum;
        __syncthreads();
        if (warp == 0) {
            float s2 = red[lane];
            for (int off = 16; off; off >>= 1)
                s2 += __shfl_xor_sync(0xffffffffu, s2, off);
            if (lane == 0) bc[1] = s2;
        }
        __syncthreads();
        float inv = 1.0f / bc[1];

        float attn = e * inv;
        out_attn[(size_t)b * NN + tid] = attn;
        float w = mask[(size_t)b * NN + tid] * attn;
        g_w[(size_t)b * NN + tid] = w;

        float ws = w;
        for (int off = 16; off; off >>= 1)
            ws += __shfl_xor_sync(0xffffffffu, ws, off);
        __syncthreads();
        if (lane == 0) red[warp] = ws;
        __syncthreads();
        if (warp == 0) {
            float s2 = red[lane];
            for (int off = 16; off; off >>= 1)
                s2 += __shfl_xor_sync(0xffffffffu, s2, off);
            if (lane == 0) g_wsum[b] = s2;
        }
    }

    grid_barrier();   // ---- w, wsum ready ----

    // ---- P5: weighted row-sum (8 rows/warp) + partial ctx matvec ----
    {
        const float* wp = &g_w[(size_t)b * NN + row0];
        float4 v[8];
        float wb[8];
#pragma unroll
        for (int jj = 0; jj < 8; jj++) {
            v[jj] = base[jj * (FF / 4) + lane];
            wb[jj] = wp[jj];
        }
        float4 acc = make_float4(0.f, 0.f, 0.f, 0.f);
#pragma unroll
        for (int jj = 0; jj < 8; jj++) {
            acc.x += wb[jj] * v[jj].x;
            acc.y += wb[jj] * v[jj].y;
            acc.z += wb[jj] * v[jj].z;
            acc.w += wb[jj] * v[jj].w;
        }
        sh4[warp][lane] = acc;
        __syncthreads();
        if (warp < 4) {
            float4 r = sh4[warp * 8][lane];
#pragma unroll
            for (int w = 1; w < 8; w++) {
                float4 x = sh4[warp * 8 + w][lane];
                r.x += x.x; r.y += x.y; r.z += x.z; r.w += x.w;
            }
            sh4[warp][lane] = r;
        }
        __syncthreads();
        if (warp == 0) {
            float4 r = sh4[0][lane];
#pragma unroll
            for (int w = 1; w < 4; w++) {
                float4 x = sh4[w][lane];
                r.x += x.x; r.y += x.y; r.z += x.z; r.w += x.w;
            }
            reinterpret_cast<float4*>(t_sh)[lane] = r;
        }
        __syncthreads();

        if (tid < DD) {
            float accd = 0.f;
#pragma unroll 8
            for (int f = 0; f < FF; f++)
                accd += t_sh[f] * Wv[(size_t)f * DD + tid];
            if (ch == 0) accd += g_wsum[b] * bv[tid];
            atomicAdd(&out_ctx[(size_t)b * DD + tid], accd);
        }
    }
}

// ---------------------------------------------------------------------------
// Inputs: atom_query, mask, Wq, bq, Wk, bk, Wv, bv
// Output: attn [B*N] then context [B*D], float32.
// ---------------------------------------------------------------------------
extern "C" void kernel_launch(void* const* d_in, const int* in_sizes, int n_in,
                              void* d_out, int out_size) {
    const float* aq   = (const float*)d_in[0];
    const float* mask = (const float*)d_in[1];
    const float* Wq   = (const float*)d_in[2];
    const float* bq   = (const float*)d_in[3];
    const float* Wk   = (const float*)d_in[4];
    const float* bk   = (const float*)d_in[5];
    const float* Wv   = (const float*)d_in[6];
    const float* bv   = (const float*)d_in[7];

    float* out_attn = (float*)d_out;
    float* out_ctx  = out_attn + (size_t)BB * NN;

    k_fused<<<NBLK, NTHR>>>(aq, mask, Wq, bq, Wk, bk, Wv, bv,
                            out_attn, out_ctx);
}

// round 7
// speedup vs baseline: 1.6514x; 1.2318x over previous
#include <cuda_runtime.h>
#include <cuda_bf16.h>

// Problem constants
#define BB 32
#define NN 1024
#define FF 128
#define DD 128
#define DK 0.08838834764831843f  // 128^{-0.5}

#define NBLK 128   // 4 chunk-blocks per batch, 256 rows each
#define NTHR 1024  // 32 warps per block

// Scratch
__device__ float g_spart[BB * 4 * FF];
__device__ float g_agg[BB * NN];      // raw (unmasked) logits
__device__ unsigned g_bar;            // monotonic ticket (replay-safe)

// ---------------------------------------------------------------------------
// Software grid barrier: monotonic ticket, generation derived from ticket.
// All NBLK=128 blocks co-resident (1 CTA/SM, 148 SMs). Release fence before
// arrive; acquire fence after release from the spin.
// ---------------------------------------------------------------------------
__device__ __forceinline__ void grid_barrier() {
    __threadfence();
    __syncthreads();
    if (threadIdx.x == 0) {
        unsigned ticket = atomicAdd(&g_bar, 1u);
        unsigned target = (ticket / NBLK + 1u) * NBLK;
        unsigned cur;
        do {
            asm volatile("ld.global.acquire.gpu.u32 %0, [%1];"
                         : "=r"(cur) : "l"(&g_bar));
        } while (cur < target);
    }
    __syncthreads();
    __threadfence();
}

__global__ __launch_bounds__(NTHR, 1) void k_fused(
        const float* __restrict__ aq,
        const float* __restrict__ mask,
        const float* __restrict__ Wq,
        const float* __restrict__ bq,
        const float* __restrict__ Wk,
        const float* __restrict__ bk,
        const float* __restrict__ Wv,
        const float* __restrict__ bv,
        float* __restrict__ out_attn,
        float* __restrict__ out_ctx) {
    int blk = blockIdx.x;
    int b   = blk >> 2;        // batch
    int ch  = blk & 3;         // 256-row chunk
    int tid = threadIdx.x;
    int lane = tid & 31;
    int warp = tid >> 5;       // 0..31, owns 8 rows of the chunk

    __shared__ float4 sh4[32][32];     // 16 KB reduce scratch
    __shared__ float  s_sh[FF];
    __shared__ float  ksum_sh[DD];
    __shared__ float  wvec_sh[FF];
    __shared__ float  t_sh[FF];
    __shared__ float  w_sh[NN];        // 4 KB: full-batch weights
    __shared__ float  ctx_part[8][DD]; // 4 KB
    __shared__ float  red[32];
    __shared__ float  bc[2];

    const float4* aq4 = reinterpret_cast<const float4*>(aq);
    int row0 = ch * 256 + warp * 8;    // row within batch for this warp
    const float4* base = aq4 + ((size_t)b * NN + row0) * (FF / 4);

    // ---- P0: zero out_ctx (poisoned by harness) ----
    if (ch == 0 && tid < DD) out_ctx[b * DD + tid] = 0.f;

    // ---- P1: row-sum own 8 rows/warp -> g_spart[b][ch] ----
    {
        float4 v[8];
#pragma unroll
        for (int jj = 0; jj < 8; jj++)
            v[jj] = base[jj * (FF / 4) + lane];
        float4 acc = v[0];
#pragma unroll
        for (int jj = 1; jj < 8; jj++) {
            acc.x += v[jj].x; acc.y += v[jj].y;
            acc.z += v[jj].z; acc.w += v[jj].w;
        }
        sh4[warp][lane] = acc;
        __syncthreads();
        if (warp < 4) {
            float4 r = sh4[warp * 8][lane];
#pragma unroll
            for (int w = 1; w < 8; w++) {
                float4 x = sh4[warp * 8 + w][lane];
                r.x += x.x; r.y += x.y; r.z += x.z; r.w += x.w;
            }
            sh4[warp][lane] = r;   // rows 0..3 written; sources are rows >= warp*8
        }
        __syncthreads();
        if (warp == 0) {
            float4 r = sh4[0][lane];
#pragma unroll
            for (int w = 1; w < 4; w++) {
                float4 x = sh4[w][lane];
                r.x += x.x; r.y += x.y; r.z += x.z; r.w += x.w;
            }
            reinterpret_cast<float4*>(&g_spart[(b * 4 + ch) * FF])[lane] = r;
        }
    }

    grid_barrier();   // ==== barrier 1: all g_spart ready ====

    // ---- P2: (redundant per block) s, ksum, wvec, cbias ----
    if (tid < FF) {
        float s = 0.f;
#pragma unroll
        for (int c2 = 0; c2 < 4; c2++)
            s += g_spart[(b * 4 + c2) * FF + tid];
        s_sh[tid] = s;
    }
    __syncthreads();
    if (tid < DD) {
        float acc = 0.f;
#pragma unroll 8
        for (int f = 0; f < FF; f++)
            acc += s_sh[f] * Wk[(size_t)f * DD + tid];
        ksum_sh[tid] = acc + (float)NN * bk[tid];
    }
    __syncthreads();
    {
#pragma unroll
        for (int j = 0; j < 4; j++) {
            int f = warp * 4 + j;
            float p = 0.f;
#pragma unroll
            for (int dd = lane; dd < DD; dd += 32)
                p += Wq[(size_t)f * DD + dd] * ksum_sh[dd];
            for (int off = 16; off; off >>= 1)
                p += __shfl_xor_sync(0xffffffffu, p, off);
            if (lane == 0) wvec_sh[f] = p;
        }
    }
    if (warp == 0) {
        float p = 0.f;
#pragma unroll
        for (int dd = lane; dd < DD; dd += 32)
            p += bq[dd] * ksum_sh[dd];
        for (int off = 16; off; off >>= 1)
            p += __shfl_xor_sync(0xffffffffu, p, off);
        if (lane == 0) bc[0] = p;
    }
    __syncthreads();

    // ---- P3: raw logits for own 8 rows/warp; coalesced 8-lane store ----
    {
        float4 wv4 = reinterpret_cast<const float4*>(wvec_sh)[lane];
        float cb = bc[0];
        float4 v[8];
#pragma unroll
        for (int jj = 0; jj < 8; jj++)
            v[jj] = base[jj * (FF / 4) + lane];
        float mine = 0.f;
#pragma unroll
        for (int jj = 0; jj < 8; jj++) {
            float d = v[jj].x * wv4.x + v[jj].y * wv4.y
                    + v[jj].z * wv4.z + v[jj].w * wv4.w;
            for (int off = 16; off; off >>= 1)
                d += __shfl_xor_sync(0xffffffffu, d, off);
            if (lane == jj) mine = DK * (d + cb);   // lane jj keeps row jj
        }
        if (lane < 8)
            g_agg[(size_t)b * NN + row0 + lane] = mine;
    }

    grid_barrier();   // ==== barrier 2: all logits ready ====

    // ---- P4: redundant full-batch softmax (every block, 1 elem/thread) ----
    {
        float m = mask[(size_t)b * NN + tid];
        float araw = g_agg[(size_t)b * NN + tid];
        float a = (m != 0.f) ? araw : -1e9f;

        float mx = a;
        for (int off = 16; off; off >>= 1)
            mx = fmaxf(mx, __shfl_xor_sync(0xffffffffu, mx, off));
        if (lane == 0) red[warp] = mx;
        __syncthreads();
        if (warp == 0) {
            float m2 = red[lane];
            for (int off = 16; off; off >>= 1)
                m2 = fmaxf(m2, __shfl_xor_sync(0xffffffffu, m2, off));
            if (lane == 0) bc[1] = m2;
        }
        __syncthreads();
        mx = bc[1];

        float e = expf(a - mx);
        float ssum = e;
        for (int off = 16; off; off >>= 1)
            ssum += __shfl_xor_sync(0xffffffffu, ssum, off);
        __syncthreads();
        if (lane == 0) red[warp] = ssum;
        __syncthreads();
        if (warp == 0) {
            float s2 = red[lane];
            for (int off = 16; off; off >>= 1)
                s2 += __shfl_xor_sync(0xffffffffu, s2, off);
            if (lane == 0) bc[1] = s2;
        }
        __syncthreads();
        float inv = 1.0f / bc[1];

        float attn = e * inv;
        if ((tid >> 8) == ch)                       // own quarter only
            out_attn[(size_t)b * NN + tid] = attn;
        float w = m * attn;
        w_sh[tid] = w;

        if (ch == 0) {  // wsum only needed for the bv term
            float ws = w;
            for (int off = 16; off; off >>= 1)
                ws += __shfl_xor_sync(0xffffffffu, ws, off);
            __syncthreads();
            if (lane == 0) red[warp] = ws;
            __syncthreads();
            if (warp == 0) {
                float s2 = red[lane];
                for (int off = 16; off; off >>= 1)
                    s2 += __shfl_xor_sync(0xffffffffu, s2, off);
                if (lane == 0) bc[0] = s2;          // wsum
            }
        }
        __syncthreads();
    }

    // ---- P5: weighted row-sum (8 rows/warp, w from shared) ----
    {
        float4 v[8];
        float wb[8];
#pragma unroll
        for (int jj = 0; jj < 8; jj++) {
            v[jj] = base[jj * (FF / 4) + lane];
            wb[jj] = w_sh[row0 + jj];               // broadcast LDS
        }
        float4 acc = make_float4(0.f, 0.f, 0.f, 0.f);
#pragma unroll
        for (int jj = 0; jj < 8; jj++) {
            acc.x += wb[jj] * v[jj].x;
            acc.y += wb[jj] * v[jj].y;
            acc.z += wb[jj] * v[jj].z;
            acc.w += wb[jj] * v[jj].w;
        }
        sh4[warp][lane] = acc;
        __syncthreads();
        if (warp < 4) {
            float4 r = sh4[warp * 8][lane];
#pragma unroll
            for (int w = 1; w < 8; w++) {
                float4 x = sh4[warp * 8 + w][lane];
                r.x += x.x; r.y += x.y; r.z += x.z; r.w += x.w;
            }
            sh4[warp][lane] = r;
        }
        __syncthreads();
        if (warp == 0) {
            float4 r = sh4[0][lane];
#pragma unroll
            for (int w = 1; w < 4; w++) {
                float4 x = sh4[w][lane];
                r.x += x.x; r.y += x.y; r.z += x.z; r.w += x.w;
            }
            reinterpret_cast<float4*>(t_sh)[lane] = r;
        }
        __syncthreads();

        // ctx matvec: 8 f-partials x 128 d across all 1024 threads
        {
            int d = tid & 127;
            int part = tid >> 7;                    // 0..7
            float acc2 = 0.f;
#pragma unroll
            for (int f = part * 16; f < part * 16 + 16; f++)
                acc2 += t_sh[f] * Wv[(size_t)f * DD + d];
            ctx_part[part][d] = acc2;
        }
        __syncthreads();
        if (tid < DD) {
            float accd = 0.f;
#pragma unroll
            for (int p = 0; p < 8; p++)
                accd += ctx_part[p][tid];
            if (ch == 0) accd += bc[0] * bv[tid];   // bc[0] = wsum
            atomicAdd(&out_ctx[(size_t)b * DD + tid], accd);
        }
    }
}

// ---------------------------------------------------------------------------
// Inputs: atom_query, mask, Wq, bq, Wk, bk, Wv, bv
// Output: attn [B*N] then context [B*D], float32.
// ---------------------------------------------------------------------------
extern "C" void kernel_launch(void* const* d_in, const int* in_sizes, int n_in,
                              void* d_out, int out_size) {
    const float* aq   = (const float*)d_in[0];
    const float* mask = (const float*)d_in[1];
    const float* Wq   = (const float*)d_in[2];
    const float* bq   = (const float*)d_in[3];
    const float* Wk   = (const float*)d_in[4];
    const float* bk   = (const float*)d_in[5];
    const float* Wv   = (const float*)d_in[6];
    const float* bv   = (const float*)d_in[7];

    float* out_attn = (float*)d_out;
    float* out_ctx  = out_attn + (size_t)BB * NN;

    k_fused<<<NBLK, NTHR>>>(aq, mask, Wq, bq, Wk, bk, Wv, bv,
                            out_attn, out_ctx);
}